// round 7
// baseline (speedup 1.0000x reference)
#include <cuda_runtime.h>
#include <cstdint>
#include <math.h>

#define NB 4
#define NN 512
#define NC 128

// logit scratch (4 MB)
__device__ float g_logits[NB * NN * NN];

__device__ __forceinline__ uint32_t f2tf32(float f) {
    uint32_t r;
    asm("cvt.rna.tf32.f32 %0, %1;" : "=r"(r) : "f"(f));
    return r;
}
__device__ __forceinline__ float lrelu(float v) { return v > 0.f ? v : 0.01f * v; }
__device__ __forceinline__ uint32_t smem_u32(const void* p) {
    uint32_t a;
    asm("{ .reg .u64 t; cvta.to.shared.u64 t, %1; cvt.u32.u64 %0, t; }" : "=r"(a) : "l"(p));
    return a;
}

// D(16x8,f32) += A(16x8,tf32,row) * B(8x8,tf32,col)
__device__ __forceinline__ void mma8(float* d, uint32_t a0, uint32_t a1, uint32_t a2, uint32_t a3,
                                     uint32_t b0, uint32_t b1) {
    asm volatile("mma.sync.aligned.m16n8k8.row.col.f32.tf32.tf32.f32 "
                 "{%0,%1,%2,%3},{%4,%5,%6,%7},{%8,%9},{%0,%1,%2,%3};"
                 : "+f"(d[0]), "+f"(d[1]), "+f"(d[2]), "+f"(d[3])
                 : "r"(a0), "r"(a1), "r"(a2), "r"(a3), "r"(b0), "r"(b1));
}

// permuted position of k within a 32-k chunk: stored p <-> logical kk=(p&7)*4+(p>>3)
__device__ __forceinline__ int perm32(int kk) { return (kk & 3) * 8 + (kk >> 2); }

#define CP_ASYNC4(dst_u32, src_ptr) \
    asm volatile("cp.async.ca.shared.global [%0], [%1], 4;" :: "r"(dst_u32), "l"(src_ptr) : "memory")
#define CP_COMMIT() asm volatile("cp.async.commit_group;" ::: "memory")
#define CP_WAIT0()  asm volatile("cp.async.wait_group 0;" ::: "memory")

// Stage chunk0 of W[N][K] (32 k's) into sW (stride 36 words, permuted) via cp.async.
__device__ __forceinline__ void stage0_async(const float* __restrict__ Wg, int N, int K,
                                             uint32_t sw_bytes, int tid) {
    int PW = N >> 4;
    for (int p = 0; p < PW; ++p) {
        int idx = tid + (p << 9);
        int n = idx >> 5, kk = idx & 31;
        CP_ASYNC4(sw_bytes + (uint32_t)((n * 36 + perm32(kk)) * 4), Wg + n * K + kk);
    }
    CP_COMMIT();
}

// Hybrid MLP layer, in-place on `buf` (tf32/fp32 words; strides SA->SO, permuted k layout).
// Warps 0-11: tf32 tensor path on cols [0, NTT*8). Warps 12-15: exact fp32 FFMA path
// on cols [NTT*8, N) — one warp per SMSP, high-wid for arbiter priority.
// Weight chunks (KC=32) double-buffered sWa/sWb via cp.async; chunk0 pre-staged in sWa.
template <int N, int K, int SA, int SO, int NTT, int NF>
__device__ void layer(uint32_t* __restrict__ buf,
                      const float* __restrict__ Wg, const float* __restrict__ bias,
                      uint32_t* __restrict__ sWa, uint32_t* __restrict__ sWb,
                      uint32_t swa_bytes, uint32_t swb_bytes, int tid)
{
    constexpr int NCH = K / 32;     // 32-k chunks
    constexpr int PW  = N / 16;     // cp.async words per thread per chunk
    constexpr int NTC = N - NF;     // tensor cols (= NTT*8)
    constexpr int CF  = NF / 4;     // FFMA cols per lane

    const int wid = tid >> 5, lane = tid & 31;

    float accu[56];                 // shared storage: tensor d[2][7][4] / FFMA acc[4][CF]
#pragma unroll
    for (int q = 0; q < 56; ++q) accu[q] = 0.f;

    // tensor warp coords
    const int g = lane >> 2, t = lane & 3;
    const int mb = (wid & 3) * 32;
    const int ng = wid >> 2;                    // 0..2 for tensor warps
    constexpr int TQ = NTT / 3, TR = NTT % 3;
    const int cnt = TQ + (ng < TR ? 1 : 0);
    const int st  = ng * TQ + (ng < TR ? ng : TR);

    // FFMA warp coords (wid 12..15)
    const int fw = wid - 12;
    const int rg = lane >> 2, cg = lane & 3;
    const int frow = fw * 32 + rg * 4;          // 4 rows per lane
    const int fcb  = NTC + cg * CF;             // CF cols per lane

    for (int c = 0; c < NCH; ++c) {
        if (c + 1 < NCH) {
            uint32_t dstb = ((c + 1) & 1) ? swb_bytes : swa_bytes;
            const float* src = Wg + (c + 1) * 32;
#pragma unroll
            for (int p = 0; p < PW; ++p) {
                int idx = tid + (p << 9);
                int n = idx >> 5, kk = idx & 31;
                CP_ASYNC4(dstb + (uint32_t)((n * 36 + perm32(kk)) * 4), src + n * K + kk);
            }
            CP_COMMIT();
        }
        const uint32_t* sWc = (c & 1) ? sWb : sWa;

        if (wid < 12) {
            // -------- tensor path: tiles st..st+cnt-1 --------
#pragma unroll
            for (int h = 0; h < 2; ++h) {
                uint32_t bf[7][4];
#pragma unroll
                for (int nt = 0; nt < 7; ++nt) {
                    if (nt < cnt) {
                        int n = (st + nt) * 8 + g;
                        *(uint4*)bf[nt] = *(const uint4*)(sWc + n * 36 + t * 8 + 4 * h);
                    }
                }
                uint32_t av[2][2][4];
#pragma unroll
                for (int mt = 0; mt < 2; ++mt) {
                    int r0 = mb + mt * 16 + g;
                    *(uint4*)av[mt][0] = *(const uint4*)(buf + r0 * SA + c * 32 + t * 8 + 4 * h);
                    *(uint4*)av[mt][1] = *(const uint4*)(buf + (r0 + 8) * SA + c * 32 + t * 8 + 4 * h);
                }
#pragma unroll
                for (int ks = 0; ks < 2; ++ks)
#pragma unroll
                    for (int mt = 0; mt < 2; ++mt)
#pragma unroll
                        for (int nt = 0; nt < 7; ++nt) {
                            if (nt < cnt)
                                mma8(&accu[(mt * 7 + nt) * 4],
                                     av[mt][0][2 * ks], av[mt][1][2 * ks],
                                     av[mt][0][2 * ks + 1], av[mt][1][2 * ks + 1],
                                     bf[nt][2 * ks], bf[nt][2 * ks + 1]);
                        }
            }
        } else {
            // -------- FFMA path: exact fp32, stored-order k pairing --------
            const float* sWf = (const float*)sWc;
            const float* Ab  = (const float*)(buf) + c * 32;
#pragma unroll
            for (int p4 = 0; p4 < 8; ++p4) {
                float4 a[4];
#pragma unroll
                for (int i = 0; i < 4; ++i)
                    a[i] = *(const float4*)(Ab + (frow + i) * SA + p4 * 4);
#pragma unroll
                for (int j = 0; j < CF; ++j) {
                    float4 w = *(const float4*)(sWf + (fcb + j) * 36 + p4 * 4);
#pragma unroll
                    for (int i = 0; i < 4; ++i) {
                        float s = accu[i * CF + j];
                        s = fmaf(a[i].x, w.x, s);
                        s = fmaf(a[i].y, w.y, s);
                        s = fmaf(a[i].z, w.z, s);
                        s = fmaf(a[i].w, w.w, s);
                        accu[i * CF + j] = s;
                    }
                }
            }
        }
        if (c + 1 < NCH) CP_WAIT0();
        __syncthreads();
    }

    // epilogue: bias + lrelu + tf32, in place, permuted columns
    if (wid < 12) {
#pragma unroll
        for (int mt = 0; mt < 2; ++mt) {
            int r0 = mb + mt * 16 + g;
#pragma unroll
            for (int nt = 0; nt < 7; ++nt) {
                if (nt < cnt) {
                    int cb = (st + nt) * 8 + 2 * t;
                    float bb0 = bias[cb], bb1 = bias[cb + 1];
                    int w0 = (cb >> 5) * 32 + perm32(cb & 31);
                    int w1 = ((cb + 1) >> 5) * 32 + perm32((cb + 1) & 31);
                    const float* d = &accu[(mt * 7 + nt) * 4];
                    buf[r0 * SO + w0]       = f2tf32(lrelu(d[0] + bb0));
                    buf[r0 * SO + w1]       = f2tf32(lrelu(d[1] + bb1));
                    buf[(r0 + 8) * SO + w0] = f2tf32(lrelu(d[2] + bb0));
                    buf[(r0 + 8) * SO + w1] = f2tf32(lrelu(d[3] + bb1));
                }
            }
        }
    } else {
#pragma unroll
        for (int i = 0; i < 4; ++i)
#pragma unroll
            for (int j = 0; j < CF; ++j) {
                int col = fcb + j;
                float v = lrelu(accu[i * CF + j] + bias[col]);
                buf[(frow + i) * SO + (col >> 5) * 32 + perm32(col & 31)] = f2tf32(v);
            }
    }
    // caller stages next chunk0 and syncs
}

extern __shared__ uint32_t dynsm[];

__global__ void __launch_bounds__(512, 1)
mlp_kernel(const float* __restrict__ x,
           const float* __restrict__ w1, const float* __restrict__ b1,
           const float* __restrict__ w2, const float* __restrict__ b2,
           const float* __restrict__ w3, const float* __restrict__ b3,
           const float* __restrict__ w4, const float* __restrict__ b4,
           const float* __restrict__ w5, const float* __restrict__ b5)
{
    __shared__ float sXi[NC];
    __shared__ float sBias[576];
    __shared__ float sW5[96];
    __shared__ float sB5;

    const int tid = threadIdx.x;

    // block -> (b, i, jt) over symmetric 128-tiles: jt >= block(i)
    int blk = blockIdx.x;
    int b = blk / 1280;
    int t = blk - b * 1280;
    int ib, local, cnt;
    if (t < 512)       { ib = 0; local = t;        cnt = 4; }
    else if (t < 896)  { ib = 1; local = t - 512;  cnt = 3; }
    else if (t < 1152) { ib = 2; local = t - 896;  cnt = 2; }
    else               { ib = 3; local = t - 1152; cnt = 1; }
    const int i  = ib * 128 + local / cnt;
    const int jt = ib + local % cnt;
    const int j0 = jt * 128;

    const float* xb = x + (size_t)b * NN * NC;

    uint32_t* buf = dynsm;                 // 128*196 words, in-place across layers
    uint32_t* sWa = buf + 128 * 196;       // 192*36 words
    uint32_t* sWb = sWa + 192 * 36;
    const uint32_t swa_bytes = smem_u32(sWa);
    const uint32_t swb_bytes = smem_u32(sWb);

    if (tid < 128) sXi[tid] = xb[(size_t)i * NC + tid];
    if (tid < 192) { sBias[tid] = b1[tid]; sBias[192 + tid] = b2[tid]; }
    if (tid < 96)  { sBias[384 + tid] = b3[tid]; sBias[480 + tid] = b4[tid]; sW5[tid] = w5[tid]; }
    if (tid == 0)  sB5 = b5[0];
    __syncthreads();   // sXi ready

    // stage w1 chunk0 while doing the prologue
    stage0_async(w1, 192, 128, swa_bytes, tid);

    // prologue: buf[r][k] = tf32(|x_i[k] - x_{j0+r}[k]|), stride 132, permuted
    for (int idx = tid; idx < 128 * 128; idx += 512) {
        int r = idx >> 7, k = idx & 127;
        float v = fabsf(sXi[k] - xb[(size_t)(j0 + r) * NC + k]);
        buf[r * 132 + (k >> 5) * 32 + perm32(k & 31)] = f2tf32(v);
    }
    CP_WAIT0();
    __syncthreads();

    layer<192, 128, 132, 196, 19, 40>(buf, w1, sBias + 0,   sWa, sWb, swa_bytes, swb_bytes, tid);
    stage0_async(w2, 192, 192, swa_bytes, tid); CP_WAIT0(); __syncthreads();
    layer<192, 192, 196, 196, 19, 40>(buf, w2, sBias + 192, sWa, sWb, swa_bytes, swb_bytes, tid);
    stage0_async(w3, 96, 192, swa_bytes, tid);  CP_WAIT0(); __syncthreads();
    layer<96, 192, 196, 100, 10, 16>(buf, w3, sBias + 384, sWa, sWb, swa_bytes, swb_bytes, tid);
    stage0_async(w4, 96, 96, swa_bytes, tid);   CP_WAIT0(); __syncthreads();
    layer<96, 96, 100, 100, 10, 16>(buf, w4, sBias + 480, sWa, sWb, swa_bytes, swb_bytes, tid);
    __syncthreads();

    // layer 5: 96 -> 1 (no activation); 4 threads per row, permuted reads
    {
        const int r = tid >> 2, q = tid & 3;
        const uint32_t* arow = buf + r * 100;
        float acc = 0.f;
#pragma unroll
        for (int k = 0; k < 24; ++k) {
            int col = q * 24 + k;
            int w = (col >> 5) * 32 + perm32(col & 31);
            acc = fmaf(__uint_as_float(arow[w]), sW5[col], acc);
        }
        acc += __shfl_xor_sync(0xffffffffu, acc, 1);
        acc += __shfl_xor_sync(0xffffffffu, acc, 2);
        if (q == 0) {
            float lg = acc + sB5;
            int j = j0 + r;
            g_logits[((size_t)b * NN + i) * NN + j] = lg;   // direct
            g_logits[((size_t)b * NN + j) * NN + i] = lg;   // mirror (d symmetric)
        }
    }
}

__global__ void __launch_bounds__(256)
softmax_kernel(float2* __restrict__ out)
{
    __shared__ float sred[8];
    __shared__ float sval;
    int row = blockIdx.x;
    int i   = row & (NN - 1);
    const float* L = g_logits + (size_t)row * NN;
    int tid  = threadIdx.x;
    int lane = tid & 31, warp = tid >> 5;

    float l0 = L[tid];
    float l1 = L[tid + 256];
    if (tid == i)       l0 -= 1e8f;
    if (tid + 256 == i) l1 -= 1e8f;

    float m = fmaxf(l0, l1);
#pragma unroll
    for (int o = 16; o > 0; o >>= 1) m = fmaxf(m, __shfl_xor_sync(0xffffffffu, m, o));
    if (lane == 0) sred[warp] = m;
    __syncthreads();
    if (tid == 0) {
        float v = sred[0];
        for (int w = 1; w < 8; ++w) v = fmaxf(v, sred[w]);
        sval = v;
    }
    __syncthreads();
    float M  = sval;
    float e0 = expf(l0 - M);
    float e1 = expf(l1 - M);
    float s  = e0 + e1;
#pragma unroll
    for (int o = 16; o > 0; o >>= 1) s += __shfl_xor_sync(0xffffffffu, s, o);
    __syncthreads();
    if (lane == 0) sred[warp] = s;
    __syncthreads();
    if (tid == 0) {
        float v = 0.f;
        for (int w = 0; w < 8; ++w) v += sred[w];
        sval = 1.0f / v;
    }
    __syncthreads();
    float inv = sval;

    float2* o2 = out + (size_t)row * NN;
    o2[tid]       = make_float2(tid == i ? 1.f : 0.f,       e0 * inv);
    o2[tid + 256] = make_float2(tid + 256 == i ? 1.f : 0.f, e1 * inv);
}

extern "C" void kernel_launch(void* const* d_in, const int* in_sizes, int n_in,
                              void* d_out, int out_size)
{
    const float* x  = (const float*)d_in[0];
    // d_in[1] = W_id (exact identity; regenerated analytically)
    const float* w1 = (const float*)d_in[2];
    const float* b1 = (const float*)d_in[3];
    const float* w2 = (const float*)d_in[4];
    const float* b2 = (const float*)d_in[5];
    const float* w3 = (const float*)d_in[6];
    const float* b3 = (const float*)d_in[7];
    const float* w4 = (const float*)d_in[8];
    const float* b4 = (const float*)d_in[9];
    const float* w5 = (const float*)d_in[10];
    const float* b5 = (const float*)d_in[11];
    float2* out = (float2*)d_out;

    // dyn smem: act buf 128x196 + 2 weight chunk buffers 192x36 = 155,648 B
    size_t smem_bytes = (128 * 196 + 2 * 192 * 36) * sizeof(uint32_t);
    cudaFuncSetAttribute(mlp_kernel, cudaFuncAttributeMaxDynamicSharedMemorySize,
                         (int)smem_bytes);

    mlp_kernel<<<NB * 1280, 512, smem_bytes>>>(
        x, w1, b1, w2, b2, w3, b3, w4, b4, w5, b5);
    softmax_kernel<<<NB * NN, 256>>>(out);
}